// round 15
// baseline (speedup 1.0000x reference)
#include <cuda_runtime.h>
#include <cuda_bf16.h>
#include <math_constants.h>
#include <cstdint>

// Problem constants (fixed by reference: B=4, L=2048, D=512, H=8)
#define B_  4
#define L_  2048
#define D_  512
#define H_  8
#define E_  64          // D/H
#define SK  40          // sample_k = 5*ceil(ln(2048)) = 40
#define UQ  40          // u_q = 40
#define BH  (B_*H_)     // 32
#define LE  (L_*E_)     // 131072  (per-(b,h) slab stride)
#define M_  (B_*L_)     // 8192 GEMM rows

// ---------------- scratch (static device globals; no allocs allowed) -------
__device__ float g_qp[B_*L_*D_];            // projected q, flat == (B,H,L,E)
__device__ float g_kp[B_*L_*D_];
__device__ float g_vp[B_*L_*D_];
__device__ float g_m[BH*L_];                // sparsity measure m[b,h,l]
__device__ int   g_mtop[BH*UQ];             // top-40 query indices per (b,h)
__device__ float g_scores[BH*UQ*L_];        // masked raw scores
__device__ float g_csum[BH*16*64];          // cumsum chunk totals

// bf16 split operands for tensor-core GEMM
__device__ __nv_bfloat16 g_xh[3u*M_*D_];
__device__ __nv_bfloat16 g_xl[3u*M_*D_];
__device__ __nv_bfloat16 g_wth[3u*D_*D_];   // W^T hi  [n][k]
__device__ __nv_bfloat16 g_wtl[3u*D_*D_];   // W^T lo

// ============================= PTX helpers (base ISA only) =================
__device__ __forceinline__ uint32_t u32smem(const void* p) {
    uint32_t a;
    asm("{ .reg .u64 t; cvta.to.shared.u64 t, %1; cvt.u32.u64 %0, t; }"
        : "=r"(a) : "l"(p));
    return a;
}
__device__ __forceinline__ void cpa16(uint32_t dst, const void* src) {
    asm volatile("cp.async.cg.shared.global [%0], [%1], 16;"
                 :: "r"(dst), "l"(src) : "memory");
}
__device__ __forceinline__ void cp_commit() {
    asm volatile("cp.async.commit_group;" ::: "memory");
}
template <int N>
__device__ __forceinline__ void cp_wait() {
    asm volatile("cp.async.wait_group %0;" :: "n"(N) : "memory");
}
__device__ __forceinline__ void ldsm_x4(uint32_t (&r)[4], uint32_t addr) {
    asm volatile("ldmatrix.sync.aligned.m8n8.x4.shared.b16 {%0,%1,%2,%3}, [%4];"
                 : "=r"(r[0]), "=r"(r[1]), "=r"(r[2]), "=r"(r[3]) : "r"(addr));
}
__device__ __forceinline__ void mma_bf16(float (&d)[4], const uint32_t (&a)[4],
                                         uint32_t b0, uint32_t b1) {
    asm volatile(
        "mma.sync.aligned.m16n8k16.row.col.f32.bf16.bf16.f32 "
        "{%0,%1,%2,%3}, {%4,%5,%6,%7}, {%8,%9}, {%0,%1,%2,%3};"
        : "+f"(d[0]), "+f"(d[1]), "+f"(d[2]), "+f"(d[3])
        : "r"(a[0]), "r"(a[1]), "r"(a[2]), "r"(a[3]), "r"(b0), "r"(b1));
}
__device__ __forceinline__ uint32_t sw128(uint32_t off) {
    return off ^ ((off >> 3) & 0x70);   // 128B-row swizzle (Swizzle<3,4,3>)
}

// ===========================================================================
// split kernels: fp32 -> (bf16 hi, bf16 lo)
// ===========================================================================
struct bf4 { __nv_bfloat16 a, b, c, d; };

__global__ __launch_bounds__(256)
void k_split_x(const float* __restrict__ q, const float* __restrict__ k,
               const float* __restrict__ v)
{
    int mat = blockIdx.y;
    const float* src = (mat == 0) ? q : (mat == 1) ? k : v;
    size_t i0 = ((size_t)blockIdx.x * 256 + threadIdx.x) * 4;
    float4 x = *(const float4*)(src + i0);
    __nv_bfloat16 h0 = __float2bfloat16(x.x), h1 = __float2bfloat16(x.y);
    __nv_bfloat16 h2 = __float2bfloat16(x.z), h3 = __float2bfloat16(x.w);
    __nv_bfloat16 l0 = __float2bfloat16(x.x - __bfloat162float(h0));
    __nv_bfloat16 l1 = __float2bfloat16(x.y - __bfloat162float(h1));
    __nv_bfloat16 l2 = __float2bfloat16(x.z - __bfloat162float(h2));
    __nv_bfloat16 l3 = __float2bfloat16(x.w - __bfloat162float(h3));
    size_t o = (size_t)mat * M_ * D_ + i0;
    bf4 hv = {h0, h1, h2, h3};
    bf4 lv = {l0, l1, l2, l3};
    *(bf4*)(g_xh + o) = hv;
    *(bf4*)(g_xl + o) = lv;
}

__global__ __launch_bounds__(256)
void k_split_w(const float* __restrict__ Wq, const float* __restrict__ Wk,
               const float* __restrict__ Wv)
{
    __shared__ float tile[32][33];
    int mat = blockIdx.z;
    const float* W = (mat == 0) ? Wq : (mat == 1) ? Wk : Wv;
    int bx = blockIdx.x, by = blockIdx.y;
    int tx = threadIdx.x & 31, ty = threadIdx.x >> 5;
    #pragma unroll
    for (int p = 0; p < 4; p++) {
        int r = by * 32 + ty + p * 8;
        tile[ty + p * 8][tx] = W[(size_t)r * D_ + bx * 32 + tx];
    }
    __syncthreads();
    size_t base = (size_t)mat * D_ * D_;
    #pragma unroll
    for (int p = 0; p < 4; p++) {
        int rt = bx * 32 + ty + p * 8;    // transposed row = original col (n)
        int ct = by * 32 + tx;            // transposed col = original row (k)
        float v = tile[tx][ty + p * 8];
        __nv_bfloat16 h = __float2bfloat16(v);
        __nv_bfloat16 l = __float2bfloat16(v - __bfloat162float(h));
        g_wth[base + (size_t)rt * D_ + ct] = h;
        g_wtl[base + (size_t)rt * D_ + ct] = l;
    }
}

// ===========================================================================
// mma.sync bf16 GEMM: P[m][n] = sum over 3 phases of Axx[m][k]*Wxx[n][k]
//   phases: (Xh,Wth) (Xh,Wtl) (Xl,Wth)  == bf16x3 fp32 emulation
// CTA 128x128, 8 warps (2x4 -> warp tile 64x32), K-chunk 64,
// 3-stage cp.async ring, ONE __syncthreads per iteration, SW128 swizzle.
// ===========================================================================
#define KT 64
#define NITER 24          // 3 phases * (512/64)
#define TILE_B (128 * 128)            // bytes per operand tile (128 rows x 128B)
#define SMEM_GEMM (6 * TILE_B)        // 3 stages x (A+B) = 96 KB dynamic

__device__ __forceinline__ void stage64(
    uint32_t smA, uint32_t smB, const __nv_bfloat16* Ap,
    const __nv_bfloat16* Bp, int m0, int n0, int kc, int tid)
{
    #pragma unroll
    for (int p = 0; p < 4; p++) {
        int idx = tid + p * 256;          // 0..1023 chunks of 16B
        int r = idx >> 3, c = idx & 7;
        uint32_t off = sw128((uint32_t)(r * 128 + c * 16));
        cpa16(smA + off, Ap + (size_t)(m0 + r) * D_ + kc + c * 8);
    }
    #pragma unroll
    for (int p = 0; p < 4; p++) {
        int idx = tid + p * 256;
        int r = idx >> 3, c = idx & 7;
        uint32_t off = sw128((uint32_t)(r * 128 + c * 16));
        cpa16(smB + off, Bp + (size_t)(n0 + r) * D_ + kc + c * 8);
    }
}

__global__ __launch_bounds__(256)
void k_gemm_mma()
{
    extern __shared__ __align__(128) char dynsm[];

    const int tid  = threadIdx.x;
    const int wid  = tid >> 5, lane = tid & 31;
    const int wm   = (wid >> 2) * 64;          // warp M offset in CTA tile
    const int wn   = (wid & 3) * 32;           // warp N offset
    const int mat  = blockIdx.z;
    const int m0   = blockIdx.y * 128;
    const int n0   = blockIdx.x * 128;

    const __nv_bfloat16* Ah = g_xh + (size_t)mat * M_ * D_;
    const __nv_bfloat16* Al = g_xl + (size_t)mat * M_ * D_;
    const __nv_bfloat16* Bh = g_wth + (size_t)mat * D_ * D_;
    const __nv_bfloat16* Bl = g_wtl + (size_t)mat * D_ * D_;
    float* P = (mat == 0) ? g_qp : (mat == 1) ? g_kp : g_vp;

    const uint32_t smb = u32smem(dynsm);
    uint32_t sA[3], sB[3];
    #pragma unroll
    for (int s = 0; s < 3; s++) {
        sA[s] = smb + (2 * s)     * TILE_B;
        sB[s] = smb + (2 * s + 1) * TILE_B;
    }

    float acc[4][4][4];
    #pragma unroll
    for (int i = 0; i < 4; i++)
        #pragma unroll
        for (int j = 0; j < 4; j++)
            #pragma unroll
            for (int r = 0; r < 4; r++) acc[i][j][r] = 0.f;

    const int lrow  = lane & 15;
    const int lcolb = (lane >> 4) * 16;        // 8 bf16 = 16 bytes

    // preload stages 0 and 1
    stage64(sA[0], sB[0], Ah, Bh, m0, n0, 0, tid);
    cp_commit();
    stage64(sA[1], sB[1], Ah, Bh, m0, n0, KT, tid);
    cp_commit();

    for (int i = 0; i < NITER; i++) {
        cp_wait<1>();                   // stage i complete
        __syncthreads();                // all threads past compute(i-1)
        int j = i + 2;
        if (j < NITER) {
            int ph = j >> 3, kc = (j & 7) * KT;
            const __nv_bfloat16* Ap = (ph < 2) ? Ah : Al;
            const __nv_bfloat16* Bp = (ph == 1) ? Bl : Bh;
            stage64(sA[j % 3], sB[j % 3], Ap, Bp, m0, n0, kc, tid);
            cp_commit();
        }
        int buf = i % 3;

        #pragma unroll
        for (int k16 = 0; k16 < 4; k16++) {
            uint32_t af[4][4];
            #pragma unroll
            for (int mt = 0; mt < 4; mt++) {
                uint32_t off = sw128((uint32_t)((wm + mt * 16 + lrow) * 128
                                                + k16 * 32 + lcolb));
                ldsm_x4(af[mt], sA[buf] + off);
            }
            uint32_t bfr[2][4];
            #pragma unroll
            for (int nt16 = 0; nt16 < 2; nt16++) {
                uint32_t off = sw128((uint32_t)((wn + nt16 * 16 + lrow) * 128
                                                + k16 * 32 + lcolb));
                ldsm_x4(bfr[nt16], sB[buf] + off);
            }
            // B reg order: 0=n0-7/k0-7, 1=n8-15/k0-7, 2=n0-7/k8-15, 3=n8-15/k8-15
            #pragma unroll
            for (int mt = 0; mt < 4; mt++)
                #pragma unroll
                for (int nt = 0; nt < 4; nt++)
                    mma_bf16(acc[mt][nt], af[mt],
                             bfr[nt >> 1][nt & 1], bfr[nt >> 1][2 + (nt & 1)]);
        }
    }

    // epilogue: direct STG.64, fragment layout rows lane/4 (+8), cols (lane%4)*2
    const int er = lane >> 2, ec = (lane & 3) * 2;
    #pragma unroll
    for (int mt = 0; mt < 4; mt++) {
        #pragma unroll
        for (int nt = 0; nt < 4; nt++) {
            size_t row = (size_t)(m0 + wm + mt * 16 + er) * D_;
            int col = n0 + wn + nt * 8 + ec;
            *(float2*)(P + row + col) =
                make_float2(acc[mt][nt][0], acc[mt][nt][1]);
            *(float2*)(P + row + 8 * D_ + col) =
                make_float2(acc[mt][nt][2], acc[mt][nt][3]);
        }
    }
}

// ===========================================================================
// Kernel 2: sparsity measure  m[b,h,l] = max_s(q.k_samp) - sum_s(q.k_samp)/L
// 8-lane groups, contiguous 128B per group-LDG (1 line per instruction).
// ksi indices prefetched with 2 coalesced loads and distributed via shuffle
// (saves ~40 broadcast-LDG wavefronts per l; bit-identical arithmetic).
// ===========================================================================
__global__ __launch_bounds__(256)
void k_measure(const int* __restrict__ ksi)
{
    int gid  = blockIdx.x * 8 + (threadIdx.x >> 5);
    int lane = threadIdx.x & 31;
    int bh = gid >> 11;
    int l  = gid & (L_ - 1);
    int g = lane >> 3, sub = lane & 7;

    const float* qrow  = g_qp + (size_t)bh * LE + (size_t)l * E_;
    const float* kslab = g_kp + (size_t)bh * LE;
    float4 q0 = *(const float4*)(qrow + sub * 4);
    float4 q1 = *(const float4*)(qrow + 32 + sub * 4);

    // coalesced ksi prefetch: lanes 0..31 hold s=lane; lanes 0..7 hold s=32+lane
    int idx_lo = __ldg(&ksi[l * SK + lane]);
    int idx_hi = (lane < SK - 32) ? __ldg(&ksi[l * SK + 32 + lane]) : 0;

    float mx = -CUDART_INF_F, sm = 0.f;
    #pragma unroll
    for (int it = 0; it < 10; it++) {
        int s = it * 4 + g;               // sample index for this 8-lane group
        int idx = (it < 8) ? __shfl_sync(0xffffffffu, idx_lo, s)
                           : __shfl_sync(0xffffffffu, idx_hi, s - 32);
        const float* kr = kslab + (size_t)idx * E_;
        float4 k0 = *(const float4*)(kr + sub * 4);
        float4 k1 = *(const float4*)(kr + 32 + sub * 4);
        float d = q0.x * k0.x + q0.y * k0.y + q0.z * k0.z + q0.w * k0.w
                + q1.x * k1.x + q1.y * k1.y + q1.z * k1.z + q1.w * k1.w;
        d += __shfl_xor_sync(0xffffffffu, d, 1);
        d += __shfl_xor_sync(0xffffffffu, d, 2);
        d += __shfl_xor_sync(0xffffffffu, d, 4);
        mx = fmaxf(mx, d);
        sm += d;
    }
    // combine the 4 groups (each holds stats over its 10 samples)
    mx = fmaxf(mx, __shfl_xor_sync(0xffffffffu, mx, 8));
    sm += __shfl_xor_sync(0xffffffffu, sm, 8);
    mx = fmaxf(mx, __shfl_xor_sync(0xffffffffu, mx, 16));
    sm += __shfl_xor_sync(0xffffffffu, sm, 16);
    if (lane == 0) g_m[gid] = mx - sm * (1.f / (float)L_);
}

// ===========================================================================
// Kernel 3: top-40 of m per (b,h).
// Init: 32 warps cache their 64-element argmax in smem.
// Loop: warp 0 ALONE extracts 40 winners — shuffle-reduce the 32 cached
// entries, knock out the winner, rescan only the owning warp's 64 elements.
// ===========================================================================
__global__ __launch_bounds__(1024)
void k_topk()
{
    __shared__ float sv[L_];
    __shared__ float wv[32];
    __shared__ int   wi[32];
    int bh = blockIdx.x;
    int t = threadIdx.x;
    int lane = t & 31, wrp = t >> 5;
    sv[t]        = g_m[bh * L_ + t];
    sv[t + 1024] = g_m[bh * L_ + t + 1024];
    __syncthreads();

    {
        int base = wrp * 64;
        float a = sv[base + lane], c = sv[base + 32 + lane];
        float best; int bi;
        if (a >= c) { best = a; bi = base + lane; }
        else        { best = c; bi = base + 32 + lane; }
        #pragma unroll
        for (int o = 16; o; o >>= 1) {
            float ov = __shfl_xor_sync(0xffffffffu, best, o);
            int   oi = __shfl_xor_sync(0xffffffffu, bi, o);
            if (ov > best || (ov == best && oi < bi)) { best = ov; bi = oi; }
        }
        if (lane == 0) { wv[wrp] = best; wi[wrp] = bi; }
    }
    __syncthreads();

    if (wrp == 0) {
        for (int it = 0; it < UQ; it++) {
            float best = wv[lane]; int bi = wi[lane];
            #pragma unroll
            for (int o = 16; o; o >>= 1) {
                float ov = __shfl_xor_sync(0xffffffffu, best, o);
                int   oi = __shfl_xor_sync(0xffffffffu, bi, o);
                if (ov > best || (ov == best && oi < bi)) { best = ov; bi = oi; }
            }
            int wstar = bi >> 6;
            if (lane == 0) {
                g_mtop[bh * UQ + it] = bi;
                sv[bi] = -CUDART_INF_F;
            }
            __syncwarp();
            int base = wstar * 64;
            float a = sv[base + lane], c = sv[base + 32 + lane];
            float nb; int ni;
            if (a >= c) { nb = a; ni = base + lane; }
            else        { nb = c; ni = base + 32 + lane; }
            #pragma unroll
            for (int o = 16; o; o >>= 1) {
                float ov = __shfl_xor_sync(0xffffffffu, nb, o);
                int   oi = __shfl_xor_sync(0xffffffffu, ni, o);
                if (ov > nb || (ov == nb && oi < ni)) { nb = ov; ni = oi; }
            }
            if (lane == 0) { wv[wstar] = nb; wi[wstar] = ni; }
            __syncwarp();
        }
    }
}

// ===========================================================================
// Kernel 4a/4b: parallel cumsum of v_ along l, written into d_out.
// ===========================================================================
__global__ __launch_bounds__(256)
void k_csum1()
{
    __shared__ float sgrp[4][64];
    int chunk = blockIdx.x, bh = blockIdx.y;
    int t = threadIdx.x, e = t & 63, g = t >> 6;
    const float* base = g_vp + (size_t)bh * LE + ((size_t)chunk * 128 + g * 32) * E_ + e;
    float s = 0.f;
    #pragma unroll
    for (int i = 0; i < 32; i++) s += base[(size_t)i * E_];
    sgrp[g][e] = s;
    __syncthreads();
    if (t < 64) {
        float tot = sgrp[0][t] + sgrp[1][t] + sgrp[2][t] + sgrp[3][t];
        g_csum[((size_t)bh * 16 + chunk) * 64 + t] = tot;
    }
}

__global__ __launch_bounds__(256)
void k_csum2(float* __restrict__ out)
{
    __shared__ float sgrp[4][64];
    int chunk = blockIdx.x, bh = blockIdx.y;
    int t = threadIdx.x, e = t & 63, g = t >> 6;
    float choff = 0.f;
    for (int c = 0; c < chunk; c++)
        choff += g_csum[((size_t)bh * 16 + c) * 64 + e];
    const float* base = g_vp + (size_t)bh * LE + ((size_t)chunk * 128 + g * 32) * E_ + e;
    float vals[32];
    #pragma unroll
    for (int i = 0; i < 32; i++) vals[i] = base[(size_t)i * E_];
    float run = 0.f;
    #pragma unroll
    for (int i = 0; i < 32; i++) { run += vals[i]; vals[i] = run; }
    sgrp[g][e] = run;
    __syncthreads();
    float off = choff;
    #pragma unroll
    for (int g2 = 0; g2 < 4; g2++) if (g2 < g) off += sgrp[g2][e];
    float* ob = out + (size_t)bh * LE + ((size_t)chunk * 128 + g * 32) * E_ + e;
    #pragma unroll
    for (int i = 0; i < 32; i++) ob[(size_t)i * E_] = vals[i] + off;
}

// ===========================================================================
// Kernel 5a: scores[u,l] = (q_top[u].k[l]) / 8, causal-masked.
// Register-blocked: each thread owns a 5u x 4l tile (8 u-blocks x 32 l-groups
// = 256 threads exactly).
// ===========================================================================
__global__ __launch_bounds__(256)
void k_scores()
{
    __shared__ float qs[UQ][64];
    __shared__ float kt[64][132];       // [e][l], pad 132 keeps float4 align
    __shared__ int   mt[UQ];
    int lt = blockIdx.x, bh = blockIdx.y;
    int l0 = lt * 128;
    int tid = threadIdx.x;
    const float* qslab = g_qp + (size_t)bh * LE;
    const float* kslab = g_kp + (size_t)bh * LE;

    if (tid < UQ) mt[tid] = g_mtop[bh * UQ + tid];
    __syncthreads();
    for (int i = tid; i < UQ * 64; i += 256) {
        int u = i >> 6, e = i & 63;
        qs[u][e] = qslab[(size_t)mt[u] * E_ + e];
    }
    for (int i = tid; i < 128 * 64; i += 256) {
        int r = i >> 6, e = i & 63;
        kt[e][r] = kslab[(size_t)(l0 + r) * E_ + e];
    }
    __syncthreads();

    const int ub = tid >> 5;            // u-block 0..7 -> u = ub*5 .. ub*5+4
    const int lq = (tid & 31) * 4;      // l-group 0..124

    float acc[5][4];
    #pragma unroll
    for (int uu = 0; uu < 5; uu++)
        #pragma unroll
        for (int c = 0; c < 4; c++) acc[uu][c] = 0.f;

    #pragma unroll 8
    for (int e = 0; e < 64; e++) {
        float4 kv = *(const float4*)&kt[e][lq];
        #pragma unroll
        for (int uu = 0; uu < 5; uu++) {
            float qv = qs[ub * 5 + uu][e];
            acc[uu][0] = fmaf(qv, kv.x, acc[uu][0]);
            acc[uu][1] = fmaf(qv, kv.y, acc[uu][1]);
            acc[uu][2] = fmaf(qv, kv.z, acc[uu][2]);
            acc[uu][3] = fmaf(qv, kv.w, acc[uu][3]);
        }
    }

    #pragma unroll
    for (int uu = 0; uu < 5; uu++) {
        int u = ub * 5 + uu;
        int mu = mt[u];
        float4 r;
        r.x = (l0 + lq + 0 > mu) ? -CUDART_INF_F : acc[uu][0] * 0.125f;
        r.y = (l0 + lq + 1 > mu) ? -CUDART_INF_F : acc[uu][1] * 0.125f;
        r.z = (l0 + lq + 2 > mu) ? -CUDART_INF_F : acc[uu][2] * 0.125f;
        r.w = (l0 + lq + 3 > mu) ? -CUDART_INF_F : acc[uu][3] * 0.125f;
        *(float4*)&g_scores[(size_t)(bh * UQ + u) * L_ + l0 + lq] = r;
    }
}

// ===========================================================================
// Kernel 5b (fused): flash-style softmax + attn@V + scatter into out.
// CTA = (4 u, bh). Running max/sum per u; accumulators rescaled per tile.
// ===========================================================================
__global__ __launch_bounds__(256)
void k_ctx(float* __restrict__ out)
{
    __shared__ float at[4][128];
    __shared__ int   mt4[4];
    __shared__ float f_s[4];
    __shared__ float S_s[4];
    __shared__ float red[4][4][64];
    int bh = blockIdx.y;
    int u0 = blockIdx.x * 4;
    int t = threadIdx.x;
    int e = t & 63, part = t >> 6;
    int lane = t & 31, w = t >> 5;
    const float* vslab = g_vp + (size_t)bh * LE;

    if (t < 4) mt4[t] = g_mtop[bh * UQ + u0 + t];
    float a0 = 0.f, a1 = 0.f, a2 = 0.f, a3 = 0.f;
    float Mrun = -CUDART_INF_F, Srun = 0.f;       // live in warps 0-3 only

    for (int lt = 0; lt < 16; lt++) {
        int l0 = lt * 128;
        __syncthreads();
        for (int i = t; i < 512; i += 256) {
            int uu = i >> 7, ll = i & 127;
            at[uu][ll] = g_scores[(size_t)(bh * UQ + u0 + uu) * L_ + l0 + ll];
        }
        __syncthreads();
        if (w < 4) {
            float x0 = at[w][lane],      x1 = at[w][lane + 32];
            float x2 = at[w][lane + 64], x3 = at[w][lane + 96];
            float m = fmaxf(fmaxf(x0, x1), fmaxf(x2, x3));
            #pragma unroll
            for (int o = 16; o; o >>= 1)
                m = fmaxf(m, __shfl_xor_sync(0xffffffffu, m, o));
            float Mnew = fmaxf(Mrun, m);
            float f = __expf(Mrun - Mnew);
            float p0 = __expf(x0 - Mnew), p1 = __expf(x1 - Mnew);
            float p2 = __expf(x2 - Mnew), p3 = __expf(x3 - Mnew);
            at[w][lane] = p0;      at[w][lane + 32] = p1;
            at[w][lane + 64] = p2; at[w][lane + 96] = p3;
            float ts = p0 + p1 + p2 + p3;
            #pragma unroll
            for (int o = 16; o; o >>= 1)
                ts += __shfl_xor_sync(0xffffffffu, ts, o);
            Srun = Srun * f + ts;
            Mrun = Mnew;
            if (lane == 0) { f_s[w] = f; S_s[w] = Srun; }
        }
        __syncthreads();
        a0 *= f_s[0]; a1 *= f_s[1]; a2 *= f_s[2]; a3 *= f_s[3];
        #pragma unroll 4
        for (int j = 0; j < 32; j++) {
            int ll = part * 32 + j;
            float v = vslab[(size_t)(l0 + ll) * E_ + e];
            a0 = fmaf(at[0][ll], v, a0);
            a1 = fmaf(at[1][ll], v, a1);
            a2 = fmaf(at[2][ll], v, a2);
            a3 = fmaf(at[3][ll], v, a3);
        }
    }
    red[0][part][e] = a0;
    red[1][part][e] = a1;
    red[2][part][e] = a2;
    red[3][part][e] = a3;
    __syncthreads();
    if (part == 0) {
        #pragma unroll
        for (int uu = 0; uu < 4; uu++) {
            float s = red[uu][0][e] + red[uu][1][e] + red[uu][2][e] + red[uu][3][e];
            out[(size_t)bh * LE + (size_t)mt4[uu] * E_ + e] = s / S_s[uu];
        }
    }
}

// ===========================================================================
extern "C" void kernel_launch(void* const* d_in, const int* in_sizes, int n_in,
                              void* d_out, int out_size)
{
    (void)in_sizes; (void)n_in; (void)out_size;
    const float* q   = (const float*)d_in[0];
    const float* k   = (const float*)d_in[1];
    const float* v   = (const float*)d_in[2];
    const float* Wq  = (const float*)d_in[3];
    const float* Wk  = (const float*)d_in[4];
    const float* Wv  = (const float*)d_in[5];
    const int*   ksi = (const int*)d_in[6];
    float* out = (float*)d_out;

    static cudaStream_t s1 = nullptr;
    static cudaEvent_t evA = nullptr, evB = nullptr, evC = nullptr, evD = nullptr;
    static bool inited = false;
    if (!inited) {
        cudaFuncSetAttribute(k_gemm_mma,
                             cudaFuncAttributeMaxDynamicSharedMemorySize,
                             SMEM_GEMM);
        cudaStreamCreateWithFlags(&s1, cudaStreamNonBlocking);
        cudaEventCreateWithFlags(&evA, cudaEventDisableTiming);
        cudaEventCreateWithFlags(&evB, cudaEventDisableTiming);
        cudaEventCreateWithFlags(&evC, cudaEventDisableTiming);
        cudaEventCreateWithFlags(&evD, cudaEventDisableTiming);
        inited = true;
    }

    // fork: split_w on side stream, split_x on main
    cudaEventRecord(evA, 0);
    cudaStreamWaitEvent(s1, evA, 0);
    k_split_w<<<dim3(16, 16, 3), 256, 0, s1>>>(Wq, Wk, Wv);
    cudaEventRecord(evB, s1);

    k_split_x<<<dim3((M_ * D_) / 1024, 3), 256>>>(q, k, v);
    cudaStreamWaitEvent(0, evB, 0);

    k_gemm_mma<<<dim3(D_ / 128, M_ / 128, 3), 256, SMEM_GEMM>>>();
    cudaEventRecord(evC, 0);

    // side chain: cumsum (vp only) overlaps measure/topk/scores
    cudaStreamWaitEvent(s1, evC, 0);
    k_csum1<<<dim3(16, BH), 256, 0, s1>>>();
    k_csum2<<<dim3(16, BH), 256, 0, s1>>>(out);
    cudaEventRecord(evD, s1);

    // main chain
    k_measure<<<(BH * L_) / 8, 256>>>(ksi);
    k_topk<<<BH, 1024>>>();
    k_scores<<<dim3(L_ / 128, BH), 256>>>();

    // join: ctx overwrites top-u rows of out, must follow csum2
    cudaStreamWaitEvent(0, evD, 0);
    k_ctx<<<dim3(UQ / 4, BH), 256>>>(out);
}

// round 16
// speedup vs baseline: 1.0230x; 1.0230x over previous
#include <cuda_runtime.h>
#include <cuda_bf16.h>
#include <math_constants.h>
#include <cstdint>

// Problem constants (fixed by reference: B=4, L=2048, D=512, H=8)
#define B_  4
#define L_  2048
#define D_  512
#define H_  8
#define E_  64          // D/H
#define SK  40          // sample_k = 5*ceil(ln(2048)) = 40
#define UQ  40          // u_q = 40
#define BH  (B_*H_)     // 32
#define LE  (L_*E_)     // 131072  (per-(b,h) slab stride)
#define M_  (B_*L_)     // 8192 GEMM rows

// ---------------- scratch (static device globals; no allocs allowed) -------
__device__ float g_qp[B_*L_*D_];            // projected q, flat == (B,H,L,E)
__device__ float g_kp[B_*L_*D_];
__device__ float g_vp[B_*L_*D_];
__device__ float g_m[BH*L_];                // sparsity measure m[b,h,l]
__device__ int   g_mtop[BH*UQ];             // top-40 query indices per (b,h)
__device__ float g_scores[BH*UQ*L_];        // masked raw scores
__device__ float g_csum[BH*16*64];          // cumsum chunk totals

// bf16 split operands for tensor-core GEMM
__device__ __nv_bfloat16 g_xh[3u*M_*D_];
__device__ __nv_bfloat16 g_xl[3u*M_*D_];
__device__ __nv_bfloat16 g_wth[3u*D_*D_];   // W^T hi  [n][k]
__device__ __nv_bfloat16 g_wtl[3u*D_*D_];   // W^T lo

// ============================= PTX helpers (base ISA only) =================
__device__ __forceinline__ uint32_t u32smem(const void* p) {
    uint32_t a;
    asm("{ .reg .u64 t; cvta.to.shared.u64 t, %1; cvt.u32.u64 %0, t; }"
        : "=r"(a) : "l"(p));
    return a;
}
__device__ __forceinline__ void cpa16(uint32_t dst, const void* src) {
    asm volatile("cp.async.cg.shared.global [%0], [%1], 16;"
                 :: "r"(dst), "l"(src) : "memory");
}
__device__ __forceinline__ void cp_commit() {
    asm volatile("cp.async.commit_group;" ::: "memory");
}
template <int N>
__device__ __forceinline__ void cp_wait() {
    asm volatile("cp.async.wait_group %0;" :: "n"(N) : "memory");
}
__device__ __forceinline__ void ldsm_x4(uint32_t (&r)[4], uint32_t addr) {
    asm volatile("ldmatrix.sync.aligned.m8n8.x4.shared.b16 {%0,%1,%2,%3}, [%4];"
                 : "=r"(r[0]), "=r"(r[1]), "=r"(r[2]), "=r"(r[3]) : "r"(addr));
}
__device__ __forceinline__ void mma_bf16(float (&d)[4], const uint32_t (&a)[4],
                                         uint32_t b0, uint32_t b1) {
    asm volatile(
        "mma.sync.aligned.m16n8k16.row.col.f32.bf16.bf16.f32 "
        "{%0,%1,%2,%3}, {%4,%5,%6,%7}, {%8,%9}, {%0,%1,%2,%3};"
        : "+f"(d[0]), "+f"(d[1]), "+f"(d[2]), "+f"(d[3])
        : "r"(a[0]), "r"(a[1]), "r"(a[2]), "r"(a[3]), "r"(b0), "r"(b1));
}
__device__ __forceinline__ uint32_t sw128(uint32_t off) {
    return off ^ ((off >> 3) & 0x70);   // 128B-row swizzle (Swizzle<3,4,3>)
}

// ===========================================================================
// split kernels: fp32 -> (bf16 hi, bf16 lo)
// ===========================================================================
struct bf4 { __nv_bfloat16 a, b, c, d; };

__global__ __launch_bounds__(256)
void k_split_x(const float* __restrict__ q, const float* __restrict__ k,
               const float* __restrict__ v)
{
    int mat = blockIdx.y;
    const float* src = (mat == 0) ? q : (mat == 1) ? k : v;
    size_t i0 = ((size_t)blockIdx.x * 256 + threadIdx.x) * 4;
    float4 x = *(const float4*)(src + i0);
    __nv_bfloat16 h0 = __float2bfloat16(x.x), h1 = __float2bfloat16(x.y);
    __nv_bfloat16 h2 = __float2bfloat16(x.z), h3 = __float2bfloat16(x.w);
    __nv_bfloat16 l0 = __float2bfloat16(x.x - __bfloat162float(h0));
    __nv_bfloat16 l1 = __float2bfloat16(x.y - __bfloat162float(h1));
    __nv_bfloat16 l2 = __float2bfloat16(x.z - __bfloat162float(h2));
    __nv_bfloat16 l3 = __float2bfloat16(x.w - __bfloat162float(h3));
    size_t o = (size_t)mat * M_ * D_ + i0;
    bf4 hv = {h0, h1, h2, h3};
    bf4 lv = {l0, l1, l2, l3};
    *(bf4*)(g_xh + o) = hv;
    *(bf4*)(g_xl + o) = lv;
}

__global__ __launch_bounds__(256)
void k_split_w(const float* __restrict__ Wq, const float* __restrict__ Wk,
               const float* __restrict__ Wv)
{
    __shared__ float tile[32][33];
    int mat = blockIdx.z;
    const float* W = (mat == 0) ? Wq : (mat == 1) ? Wk : Wv;
    int bx = blockIdx.x, by = blockIdx.y;
    int tx = threadIdx.x & 31, ty = threadIdx.x >> 5;
    #pragma unroll
    for (int p = 0; p < 4; p++) {
        int r = by * 32 + ty + p * 8;
        tile[ty + p * 8][tx] = W[(size_t)r * D_ + bx * 32 + tx];
    }
    __syncthreads();
    size_t base = (size_t)mat * D_ * D_;
    #pragma unroll
    for (int p = 0; p < 4; p++) {
        int rt = bx * 32 + ty + p * 8;    // transposed row = original col (n)
        int ct = by * 32 + tx;            // transposed col = original row (k)
        float v = tile[tx][ty + p * 8];
        __nv_bfloat16 h = __float2bfloat16(v);
        __nv_bfloat16 l = __float2bfloat16(v - __bfloat162float(h));
        g_wth[base + (size_t)rt * D_ + ct] = h;
        g_wtl[base + (size_t)rt * D_ + ct] = l;
    }
}

// ===========================================================================
// mma.sync bf16 GEMM: P[m][n] = sum over 3 phases of Axx[m][k]*Wxx[n][k]
//   phases: (Xh,Wth) (Xh,Wtl) (Xl,Wth)  == bf16x3 fp32 emulation
// CTA 128x128, 8 warps (2x4 -> warp tile 64x32), K-chunk 64,
// 3-stage cp.async ring, ONE __syncthreads per iteration, SW128 swizzle.
// ===========================================================================
#define KT 64
#define NITER 24          // 3 phases * (512/64)
#define TILE_B (128 * 128)            // bytes per operand tile (128 rows x 128B)
#define SMEM_GEMM (6 * TILE_B)        // 3 stages x (A+B) = 96 KB dynamic

__device__ __forceinline__ void stage64(
    uint32_t smA, uint32_t smB, const __nv_bfloat16* Ap,
    const __nv_bfloat16* Bp, int m0, int n0, int kc, int tid)
{
    #pragma unroll
    for (int p = 0; p < 4; p++) {
        int idx = tid + p * 256;          // 0..1023 chunks of 16B
        int r = idx >> 3, c = idx & 7;
        uint32_t off = sw128((uint32_t)(r * 128 + c * 16));
        cpa16(smA + off, Ap + (size_t)(m0 + r) * D_ + kc + c * 8);
    }
    #pragma unroll
    for (int p = 0; p < 4; p++) {
        int idx = tid + p * 256;
        int r = idx >> 3, c = idx & 7;
        uint32_t off = sw128((uint32_t)(r * 128 + c * 16));
        cpa16(smB + off, Bp + (size_t)(n0 + r) * D_ + kc + c * 8);
    }
}

__global__ __launch_bounds__(256)
void k_gemm_mma()
{
    extern __shared__ __align__(128) char dynsm[];

    const int tid  = threadIdx.x;
    const int wid  = tid >> 5, lane = tid & 31;
    const int wm   = (wid >> 2) * 64;          // warp M offset in CTA tile
    const int wn   = (wid & 3) * 32;           // warp N offset
    const int mat  = blockIdx.z;
    const int m0   = blockIdx.y * 128;
    const int n0   = blockIdx.x * 128;

    const __nv_bfloat16* Ah = g_xh + (size_t)mat * M_ * D_;
    const __nv_bfloat16* Al = g_xl + (size_t)mat * M_ * D_;
    const __nv_bfloat16* Bh = g_wth + (size_t)mat * D_ * D_;
    const __nv_bfloat16* Bl = g_wtl + (size_t)mat * D_ * D_;
    float* P = (mat == 0) ? g_qp : (mat == 1) ? g_kp : g_vp;

    const uint32_t smb = u32smem(dynsm);
    uint32_t sA[3], sB[3];
    #pragma unroll
    for (int s = 0; s < 3; s++) {
        sA[s] = smb + (2 * s)     * TILE_B;
        sB[s] = smb + (2 * s + 1) * TILE_B;
    }

    float acc[4][4][4];
    #pragma unroll
    for (int i = 0; i < 4; i++)
        #pragma unroll
        for (int j = 0; j < 4; j++)
            #pragma unroll
            for (int r = 0; r < 4; r++) acc[i][j][r] = 0.f;

    const int lrow  = lane & 15;
    const int lcolb = (lane >> 4) * 16;        // 8 bf16 = 16 bytes

    // preload stages 0 and 1
    stage64(sA[0], sB[0], Ah, Bh, m0, n0, 0, tid);
    cp_commit();
    stage64(sA[1], sB[1], Ah, Bh, m0, n0, KT, tid);
    cp_commit();

    for (int i = 0; i < NITER; i++) {
        cp_wait<1>();                   // stage i complete
        __syncthreads();                // all threads past compute(i-1)
        int j = i + 2;
        if (j < NITER) {
            int ph = j >> 3, kc = (j & 7) * KT;
            const __nv_bfloat16* Ap = (ph < 2) ? Ah : Al;
            const __nv_bfloat16* Bp = (ph == 1) ? Bl : Bh;
            stage64(sA[j % 3], sB[j % 3], Ap, Bp, m0, n0, kc, tid);
            cp_commit();
        }
        int buf = i % 3;

        #pragma unroll
        for (int k16 = 0; k16 < 4; k16++) {
            uint32_t af[4][4];
            #pragma unroll
            for (int mt = 0; mt < 4; mt++) {
                uint32_t off = sw128((uint32_t)((wm + mt * 16 + lrow) * 128
                                                + k16 * 32 + lcolb));
                ldsm_x4(af[mt], sA[buf] + off);
            }
            uint32_t bfr[2][4];
            #pragma unroll
            for (int nt16 = 0; nt16 < 2; nt16++) {
                uint32_t off = sw128((uint32_t)((wn + nt16 * 16 + lrow) * 128
                                                + k16 * 32 + lcolb));
                ldsm_x4(bfr[nt16], sB[buf] + off);
            }
            // B reg order: 0=n0-7/k0-7, 1=n8-15/k0-7, 2=n0-7/k8-15, 3=n8-15/k8-15
            #pragma unroll
            for (int mt = 0; mt < 4; mt++)
                #pragma unroll
                for (int nt = 0; nt < 4; nt++)
                    mma_bf16(acc[mt][nt], af[mt],
                             bfr[nt >> 1][nt & 1], bfr[nt >> 1][2 + (nt & 1)]);
        }
    }

    // epilogue: direct STG.64, fragment layout rows lane/4 (+8), cols (lane%4)*2
    const int er = lane >> 2, ec = (lane & 3) * 2;
    #pragma unroll
    for (int mt = 0; mt < 4; mt++) {
        #pragma unroll
        for (int nt = 0; nt < 4; nt++) {
            size_t row = (size_t)(m0 + wm + mt * 16 + er) * D_;
            int col = n0 + wn + nt * 8 + ec;
            *(float2*)(P + row + col) =
                make_float2(acc[mt][nt][0], acc[mt][nt][1]);
            *(float2*)(P + row + 8 * D_ + col) =
                make_float2(acc[mt][nt][2], acc[mt][nt][3]);
        }
    }
}

// ===========================================================================
// Kernel 2: sparsity measure  m[b,h,l] = max_s(q.k_samp) - sum_s(q.k_samp)/L
// 8-lane groups, contiguous 128B per group-LDG (1 line per instruction).
// ===========================================================================
__global__ __launch_bounds__(256)
void k_measure(const int* __restrict__ ksi)
{
    int gid  = blockIdx.x * 8 + (threadIdx.x >> 5);
    int lane = threadIdx.x & 31;
    int bh = gid >> 11;
    int l  = gid & (L_ - 1);
    int g = lane >> 3, sub = lane & 7;

    const float* qrow  = g_qp + (size_t)bh * LE + (size_t)l * E_;
    const float* kslab = g_kp + (size_t)bh * LE;
    float4 q0 = *(const float4*)(qrow + sub * 4);
    float4 q1 = *(const float4*)(qrow + 32 + sub * 4);

    float mx = -CUDART_INF_F, sm = 0.f;
    #pragma unroll
    for (int it = 0; it < 10; it++) {
        int s = it * 4 + g;
        int idx = __ldg(&ksi[l * SK + s]);
        const float* kr = kslab + (size_t)idx * E_;
        float4 k0 = *(const float4*)(kr + sub * 4);
        float4 k1 = *(const float4*)(kr + 32 + sub * 4);
        float d = q0.x * k0.x + q0.y * k0.y + q0.z * k0.z + q0.w * k0.w
                + q1.x * k1.x + q1.y * k1.y + q1.z * k1.z + q1.w * k1.w;
        d += __shfl_xor_sync(0xffffffffu, d, 1);
        d += __shfl_xor_sync(0xffffffffu, d, 2);
        d += __shfl_xor_sync(0xffffffffu, d, 4);
        mx = fmaxf(mx, d);
        sm += d;
    }
    // combine the 4 groups (each holds stats over its 10 samples)
    mx = fmaxf(mx, __shfl_xor_sync(0xffffffffu, mx, 8));
    sm += __shfl_xor_sync(0xffffffffu, sm, 8);
    mx = fmaxf(mx, __shfl_xor_sync(0xffffffffu, mx, 16));
    sm += __shfl_xor_sync(0xffffffffu, sm, 16);
    if (lane == 0) g_m[gid] = mx - sm * (1.f / (float)L_);
}

// ===========================================================================
// Kernel 3: top-40 of m per (b,h).
// Init: 32 warps cache their 64-element argmax in smem.
// Loop: warp 0 ALONE extracts 40 winners — shuffle-reduce the 32 cached
// entries, knock out the winner, rescan only the owning warp's 64 elements.
// No __syncthreads in the loop (only __syncwarp).
// ===========================================================================
__global__ __launch_bounds__(1024)
void k_topk()
{
    __shared__ float sv[L_];
    __shared__ float wv[32];
    __shared__ int   wi[32];
    int bh = blockIdx.x;
    int t = threadIdx.x;
    int lane = t & 31, wrp = t >> 5;
    sv[t]        = g_m[bh * L_ + t];
    sv[t + 1024] = g_m[bh * L_ + t + 1024];
    __syncthreads();

    // per-warp argmax over its 64 elements: warp w owns [w*64, w*64+64)
    {
        int base = wrp * 64;
        float a = sv[base + lane], c = sv[base + 32 + lane];
        float best; int bi;
        if (a >= c) { best = a; bi = base + lane; }
        else        { best = c; bi = base + 32 + lane; }
        #pragma unroll
        for (int o = 16; o; o >>= 1) {
            float ov = __shfl_xor_sync(0xffffffffu, best, o);
            int   oi = __shfl_xor_sync(0xffffffffu, bi, o);
            if (ov > best || (ov == best && oi < bi)) { best = ov; bi = oi; }
        }
        if (lane == 0) { wv[wrp] = best; wi[wrp] = bi; }
    }
    __syncthreads();

    if (wrp == 0) {
        for (int it = 0; it < UQ; it++) {
            float best = wv[lane]; int bi = wi[lane];
            #pragma unroll
            for (int o = 16; o; o >>= 1) {
                float ov = __shfl_xor_sync(0xffffffffu, best, o);
                int   oi = __shfl_xor_sync(0xffffffffu, bi, o);
                if (ov > best || (ov == best && oi < bi)) { best = ov; bi = oi; }
            }
            // butterfly reduce converges: all lanes hold the global winner
            int wstar = bi >> 6;
            if (lane == 0) {
                g_mtop[bh * UQ + it] = bi;
                sv[bi] = -CUDART_INF_F;
            }
            __syncwarp();
            // rescan warp wstar's 64 elements
            int base = wstar * 64;
            float a = sv[base + lane], c = sv[base + 32 + lane];
            float nb; int ni;
            if (a >= c) { nb = a; ni = base + lane; }
            else        { nb = c; ni = base + 32 + lane; }
            #pragma unroll
            for (int o = 16; o; o >>= 1) {
                float ov = __shfl_xor_sync(0xffffffffu, nb, o);
                int   oi = __shfl_xor_sync(0xffffffffu, ni, o);
                if (ov > nb || (ov == nb && oi < ni)) { nb = ov; ni = oi; }
            }
            if (lane == 0) { wv[wstar] = nb; wi[wstar] = ni; }
            __syncwarp();
        }
    }
}

// ===========================================================================
// Kernel 4a/4b: parallel cumsum of v_ along l, written into d_out.
// ===========================================================================
__global__ __launch_bounds__(256)
void k_csum1()
{
    __shared__ float sgrp[4][64];
    int chunk = blockIdx.x, bh = blockIdx.y;
    int t = threadIdx.x, e = t & 63, g = t >> 6;
    const float* base = g_vp + (size_t)bh * LE + ((size_t)chunk * 128 + g * 32) * E_ + e;
    float s = 0.f;
    #pragma unroll
    for (int i = 0; i < 32; i++) s += base[(size_t)i * E_];
    sgrp[g][e] = s;
    __syncthreads();
    if (t < 64) {
        float tot = sgrp[0][t] + sgrp[1][t] + sgrp[2][t] + sgrp[3][t];
        g_csum[((size_t)bh * 16 + chunk) * 64 + t] = tot;
    }
}

__global__ __launch_bounds__(256)
void k_csum2(float* __restrict__ out)
{
    __shared__ float sgrp[4][64];
    int chunk = blockIdx.x, bh = blockIdx.y;
    int t = threadIdx.x, e = t & 63, g = t >> 6;
    float choff = 0.f;
    for (int c = 0; c < chunk; c++)
        choff += g_csum[((size_t)bh * 16 + c) * 64 + e];
    const float* base = g_vp + (size_t)bh * LE + ((size_t)chunk * 128 + g * 32) * E_ + e;
    float vals[32];
    #pragma unroll
    for (int i = 0; i < 32; i++) vals[i] = base[(size_t)i * E_];
    float run = 0.f;
    #pragma unroll
    for (int i = 0; i < 32; i++) { run += vals[i]; vals[i] = run; }
    sgrp[g][e] = run;
    __syncthreads();
    float off = choff;
    #pragma unroll
    for (int g2 = 0; g2 < 4; g2++) if (g2 < g) off += sgrp[g2][e];
    float* ob = out + (size_t)bh * LE + ((size_t)chunk * 128 + g * 32) * E_ + e;
    #pragma unroll
    for (int i = 0; i < 32; i++) ob[(size_t)i * E_] = vals[i] + off;
}

// ===========================================================================
// Kernel 5a: scores[u,l] = (q_top[u].k[l]) / 8, causal-masked.
// Register-blocked: each thread owns a 5u x 4l tile (8 u-blocks x 32 l-groups
// = 256 threads exactly).
// ===========================================================================
__global__ __launch_bounds__(256)
void k_scores()
{
    __shared__ float qs[UQ][64];
    __shared__ float kt[64][132];       // [e][l], pad 132 keeps float4 align
    __shared__ int   mt[UQ];
    int lt = blockIdx.x, bh = blockIdx.y;
    int l0 = lt * 128;
    int tid = threadIdx.x;
    const float* qslab = g_qp + (size_t)bh * LE;
    const float* kslab = g_kp + (size_t)bh * LE;

    if (tid < UQ) mt[tid] = g_mtop[bh * UQ + tid];
    __syncthreads();
    for (int i = tid; i < UQ * 64; i += 256) {
        int u = i >> 6, e = i & 63;
        qs[u][e] = qslab[(size_t)mt[u] * E_ + e];
    }
    for (int i = tid; i < 128 * 64; i += 256) {
        int r = i >> 6, e = i & 63;
        kt[e][r] = kslab[(size_t)(l0 + r) * E_ + e];
    }
    __syncthreads();

    const int ub = tid >> 5;            // u-block 0..7 -> u = ub*5 .. ub*5+4
    const int lq = (tid & 31) * 4;      // l-group 0..124

    float acc[5][4];
    #pragma unroll
    for (int uu = 0; uu < 5; uu++)
        #pragma unroll
        for (int c = 0; c < 4; c++) acc[uu][c] = 0.f;

    #pragma unroll 8
    for (int e = 0; e < 64; e++) {
        float4 kv = *(const float4*)&kt[e][lq];
        #pragma unroll
        for (int uu = 0; uu < 5; uu++) {
            float qv = qs[ub * 5 + uu][e];
            acc[uu][0] = fmaf(qv, kv.x, acc[uu][0]);
            acc[uu][1] = fmaf(qv, kv.y, acc[uu][1]);
            acc[uu][2] = fmaf(qv, kv.z, acc[uu][2]);
            acc[uu][3] = fmaf(qv, kv.w, acc[uu][3]);
        }
    }

    #pragma unroll
    for (int uu = 0; uu < 5; uu++) {
        int u = ub * 5 + uu;
        int mu = mt[u];
        float4 r;
        r.x = (l0 + lq + 0 > mu) ? -CUDART_INF_F : acc[uu][0] * 0.125f;
        r.y = (l0 + lq + 1 > mu) ? -CUDART_INF_F : acc[uu][1] * 0.125f;
        r.z = (l0 + lq + 2 > mu) ? -CUDART_INF_F : acc[uu][2] * 0.125f;
        r.w = (l0 + lq + 3 > mu) ? -CUDART_INF_F : acc[uu][3] * 0.125f;
        *(float4*)&g_scores[(size_t)(bh * UQ + u) * L_ + l0 + lq] = r;
    }
}

// ===========================================================================
// Kernel 5b (fused): flash-style softmax + attn@V + scatter into out.
// CTA = (4 u, bh). Running max/sum per u; accumulators rescaled per tile.
// ===========================================================================
__global__ __launch_bounds__(256)
void k_ctx(float* __restrict__ out)
{
    __shared__ float at[4][128];
    __shared__ int   mt4[4];
    __shared__ float f_s[4];
    __shared__ float S_s[4];
    __shared__ float red[4][4][64];
    int bh = blockIdx.y;
    int u0 = blockIdx.x * 4;
    int t = threadIdx.x;
    int e = t & 63, part = t >> 6;
    int lane = t & 31, w = t >> 5;
    const float* vslab = g_vp + (size_t)bh * LE;

    if (t < 4) mt4[t] = g_mtop[bh * UQ + u0 + t];
    float a0 = 0.f, a1 = 0.f, a2 = 0.f, a3 = 0.f;
    float Mrun = -CUDART_INF_F, Srun = 0.f;       // live in warps 0-3 only

    for (int lt = 0; lt < 16; lt++) {
        int l0 = lt * 128;
        __syncthreads();
        for (int i = t; i < 512; i += 256) {
            int uu = i >> 7, ll = i & 127;
            at[uu][ll] = g_scores[(size_t)(bh * UQ + u0 + uu) * L_ + l0 + ll];
        }
        __syncthreads();
        if (w < 4) {
            // warp w owns u = w: tile max, exp in place, tile sum
            float x0 = at[w][lane],      x1 = at[w][lane + 32];
            float x2 = at[w][lane + 64], x3 = at[w][lane + 96];
            float m = fmaxf(fmaxf(x0, x1), fmaxf(x2, x3));
            #pragma unroll
            for (int o = 16; o; o >>= 1)
                m = fmaxf(m, __shfl_xor_sync(0xffffffffu, m, o));
            float Mnew = fmaxf(Mrun, m);
            float f = __expf(Mrun - Mnew);          // 0 on first finite tile
            float p0 = __expf(x0 - Mnew), p1 = __expf(x1 - Mnew);
            float p2 = __expf(x2 - Mnew), p3 = __expf(x3 - Mnew);
            at[w][lane] = p0;      at[w][lane + 32] = p1;
            at[w][lane + 64] = p2; at[w][lane + 96] = p3;
            float ts = p0 + p1 + p2 + p3;
            #pragma unroll
            for (int o = 16; o; o >>= 1)
                ts += __shfl_xor_sync(0xffffffffu, ts, o);
            Srun = Srun * f + ts;
            Mrun = Mnew;
            if (lane == 0) { f_s[w] = f; S_s[w] = Srun; }
        }
        __syncthreads();
        a0 *= f_s[0]; a1 *= f_s[1]; a2 *= f_s[2]; a3 *= f_s[3];
        #pragma unroll 4
        for (int j = 0; j < 32; j++) {
            int ll = part * 32 + j;
            float v = vslab[(size_t)(l0 + ll) * E_ + e];
            a0 = fmaf(at[0][ll], v, a0);
            a1 = fmaf(at[1][ll], v, a1);
            a2 = fmaf(at[2][ll], v, a2);
            a3 = fmaf(at[3][ll], v, a3);
        }
    }
    red[0][part][e] = a0;
    red[1][part][e] = a1;
    red[2][part][e] = a2;
    red[3][part][e] = a3;
    __syncthreads();
    if (part == 0) {
        #pragma unroll
        for (int uu = 0; uu < 4; uu++) {
            float s = red[uu][0][e] + red[uu][1][e] + red[uu][2][e] + red[uu][3][e];
            out[(size_t)bh * LE + (size_t)mt4[uu] * E_ + e] = s / S_s[uu];
        }
    }
}

// ===========================================================================
extern "C" void kernel_launch(void* const* d_in, const int* in_sizes, int n_in,
                              void* d_out, int out_size)
{
    (void)in_sizes; (void)n_in; (void)out_size;
    const float* q   = (const float*)d_in[0];
    const float* k   = (const float*)d_in[1];
    const float* v   = (const float*)d_in[2];
    const float* Wq  = (const float*)d_in[3];
    const float* Wk  = (const float*)d_in[4];
    const float* Wv  = (const float*)d_in[5];
    const int*   ksi = (const int*)d_in[6];
    float* out = (float*)d_out;

    static cudaStream_t s1 = nullptr;
    static cudaEvent_t evA = nullptr, evB = nullptr, evC = nullptr, evD = nullptr;
    static bool inited = false;
    if (!inited) {
        cudaFuncSetAttribute(k_gemm_mma,
                             cudaFuncAttributeMaxDynamicSharedMemorySize,
                             SMEM_GEMM);
        cudaStreamCreateWithFlags(&s1, cudaStreamNonBlocking);
        cudaEventCreateWithFlags(&evA, cudaEventDisableTiming);
        cudaEventCreateWithFlags(&evB, cudaEventDisableTiming);
        cudaEventCreateWithFlags(&evC, cudaEventDisableTiming);
        cudaEventCreateWithFlags(&evD, cudaEventDisableTiming);
        inited = true;
    }

    // fork: split_w on side stream, split_x on main
    cudaEventRecord(evA, 0);
    cudaStreamWaitEvent(s1, evA, 0);
    k_split_w<<<dim3(16, 16, 3), 256, 0, s1>>>(Wq, Wk, Wv);
    cudaEventRecord(evB, s1);

    k_split_x<<<dim3((M_ * D_) / 1024, 3), 256>>>(q, k, v);
    cudaStreamWaitEvent(0, evB, 0);

    k_gemm_mma<<<dim3(D_ / 128, M_ / 128, 3), 256, SMEM_GEMM>>>();
    cudaEventRecord(evC, 0);

    // side chain: cumsum (vp only) overlaps measure/topk/scores
    cudaStreamWaitEvent(s1, evC, 0);
    k_csum1<<<dim3(16, BH), 256, 0, s1>>>();
    k_csum2<<<dim3(16, BH), 256, 0, s1>>>(out);
    cudaEventRecord(evD, s1);

    // main chain
    k_measure<<<(BH * L_) / 8, 256>>>(ksi);
    k_topk<<<BH, 1024>>>();
    k_scores<<<dim3(L_ / 128, BH), 256>>>();

    // join: ctx overwrites top-u rows of out, must follow csum2
    cudaStreamWaitEvent(0, evD, 0);
    k_ctx<<<dim3(UQ / 4, BH), 256>>>(out);
}